// round 1
// baseline (speedup 1.0000x reference)
#include <cuda_runtime.h>

#define BATCH 128
#define NAG   64
#define NEDGE 4032
#define DN    16
#define HDIM  64
#define DOUT  16

// Scratch (no cudaMalloc allowed): per-(b,node) factored layer-1 terms + node messages.
__device__ float g_A0[BATCH * NAG * HDIM];
__device__ float g_C0[BATCH * NAG * HDIM];
__device__ float g_A1[BATCH * NAG * HDIM];
__device__ float g_C1[BATCH * NAG * HDIM];
__device__ float g_msg[BATCH * NAG * HDIM];

// K1: per (b,n): A_t = x @ W1_t[:16],  C_t = x @ W1_t[16:] + b1_t
__global__ __launch_bounds__(64) void k1_precompute(
    const float* __restrict__ x,
    const float* __restrict__ e0w1, const float* __restrict__ e0b1,
    const float* __restrict__ e1w1, const float* __restrict__ e1b1)
{
    int bn = blockIdx.x;      // b*64 + n
    int j  = threadIdx.x;     // 0..63 hidden dim
    __shared__ float xs[DN];
    if (j < DN) xs[j] = x[bn * DN + j];
    __syncthreads();

    float a0 = 0.f, a1 = 0.f;
    float c0 = e0b1[j], c1 = e1b1[j];
#pragma unroll
    for (int i = 0; i < DN; i++) {
        float xv = xs[i];
        a0 += xv * e0w1[i * HDIM + j];
        c0 += xv * e0w1[(DN + i) * HDIM + j];
        a1 += xv * e1w1[i * HDIM + j];
        c1 += xv * e1w1[(DN + i) * HDIM + j];
    }
    g_A0[bn * HDIM + j] = a0;
    g_C0[bn * HDIM + j] = c0;
    g_A1[bn * HDIM + j] = a1;
    g_C1[bn * HDIM + j] = c1;
}

// K2: one block per (b, recv). Thread j owns output dim j, keeps W2 columns in regs.
// msg[b,r,j] = sum_{s != r} sum_t w_t(b,e) * relu( relu(A_t[b,s]+C_t[b,r]) . W2_t[:,j] + b2_t[j] )
__global__ __launch_bounds__(64) void k2_edges(
    const float* __restrict__ etypes,
    const float* __restrict__ e0w2, const float* __restrict__ e0b2,
    const float* __restrict__ e1w2, const float* __restrict__ e1b2)
{
    int br = blockIdx.x;
    int b  = br >> 6;
    int r  = br & 63;
    int j  = threadIdx.x;

    __shared__ float h0[HDIM];
    __shared__ float h1[HDIM];

    // Register-cache both weight columns (64+64 regs).
    float w0[HDIM], w1[HDIM];
#pragma unroll
    for (int i = 0; i < HDIM; i++) {
        w0[i] = e0w2[i * HDIM + j];
        w1[i] = e1w2[i * HDIM + j];
    }

    float c0  = g_C0[br * HDIM + j];
    float c1  = g_C1[br * HDIM + j];
    float b20 = e0b2[j];
    float b21 = e1b2[j];

    const float* A0b = g_A0 + (long)(b * NAG) * HDIM;
    const float* A1b = g_A1 + (long)(b * NAG) * HDIM;
    const float* etb = etypes + (long)b * NEDGE * 3;

    float msg = 0.f;

    for (int s = 0; s < NAG; s++) {
        if (s == r) continue;                       // uniform across block
        int e = s * 63 + r - (r > s ? 1 : 0);       // np.where(ones-eye) ordering
        float wt0 = etb[e * 3 + 1];                 // skip type-0 "no edge"
        float wt1 = etb[e * 3 + 2];

        __syncthreads();                            // protect prev-iter reads of h
        h0[j] = fmaxf(A0b[s * HDIM + j] + c0, 0.f);
        h1[j] = fmaxf(A1b[s * HDIM + j] + c1, 0.f);
        __syncthreads();

        float y0a = 0.f, y0b = 0.f, y1a = 0.f, y1b = 0.f;
#pragma unroll
        for (int i = 0; i < HDIM; i += 2) {
            y0a += h0[i]     * w0[i];
            y0b += h0[i + 1] * w0[i + 1];
            y1a += h1[i]     * w1[i];
            y1b += h1[i + 1] * w1[i + 1];
        }
        float y0 = y0a + y0b;
        float y1 = y1a + y1b;
        msg += wt0 * fmaxf(y0 + b20, 0.f) + wt1 * fmaxf(y1 + b21, 0.f);
    }

    g_msg[br * HDIM + j] = msg;
}

// K3: decoder per (b,n): relu(relu([x, msg] @ W1 + b1) @ W2 + b2)
__global__ __launch_bounds__(64) void k3_decode(
    const float* __restrict__ x,
    const float* __restrict__ ndw1, const float* __restrict__ ndb1,
    const float* __restrict__ ndw2, const float* __restrict__ ndb2,
    float* __restrict__ out)
{
    int bn = blockIdx.x;
    int j  = threadIdx.x;
    __shared__ float xs[DN];
    __shared__ float ms[HDIM];
    __shared__ float hs[HDIM];

    if (j < DN) xs[j] = x[bn * DN + j];
    ms[j] = g_msg[bn * HDIM + j];
    __syncthreads();

    float h = ndb1[j];
#pragma unroll
    for (int i = 0; i < DN; i++)   h += xs[i] * ndw1[i * HDIM + j];
#pragma unroll
    for (int i = 0; i < HDIM; i++) h += ms[i] * ndw1[(DN + i) * HDIM + j];
    hs[j] = fmaxf(h, 0.f);
    __syncthreads();

    if (j < DOUT) {
        float o = ndb2[j];
#pragma unroll
        for (int i = 0; i < HDIM; i++) o += hs[i] * ndw2[i * DOUT + j];
        out[bn * DOUT + j] = fmaxf(o, 0.f);
    }
}

extern "C" void kernel_launch(void* const* d_in, const int* in_sizes, int n_in,
                              void* d_out, int out_size)
{
    const float* node_states = (const float*)d_in[0];
    const float* edge_types  = (const float*)d_in[1];
    const float* e0_w1 = (const float*)d_in[2];
    const float* e0_b1 = (const float*)d_in[3];
    const float* e0_w2 = (const float*)d_in[4];
    const float* e0_b2 = (const float*)d_in[5];
    const float* e1_w1 = (const float*)d_in[6];
    const float* e1_b1 = (const float*)d_in[7];
    const float* e1_w2 = (const float*)d_in[8];
    const float* e1_b2 = (const float*)d_in[9];
    const float* nd_w1 = (const float*)d_in[10];
    const float* nd_b1 = (const float*)d_in[11];
    const float* nd_w2 = (const float*)d_in[12];
    const float* nd_b2 = (const float*)d_in[13];
    float* out = (float*)d_out;

    dim3 grid(BATCH * NAG);
    k1_precompute<<<grid, 64>>>(node_states, e0_w1, e0_b1, e1_w1, e1_b1);
    k2_edges<<<grid, 64>>>(edge_types, e0_w2, e0_b2, e1_w2, e1_b2);
    k3_decode<<<grid, 64>>>(node_states, nd_w1, nd_b1, nd_w2, nd_b2, out);
}

// round 2
// speedup vs baseline: 1.2327x; 1.2327x over previous
#include <cuda_runtime.h>

#define BATCH 128
#define NAG   64
#define NEDGE 4032
#define DN    16
#define HDIM  64
#define DOUT  16
#define SG    4          // senders per sync-group in k2

typedef unsigned long long u64;

// Scratch (no cudaMalloc allowed)
__device__ float g_A0[BATCH * NAG * HDIM];
__device__ float g_C0[BATCH * NAG * HDIM];
__device__ float g_A1[BATCH * NAG * HDIM];
__device__ float g_C1[BATCH * NAG * HDIM];
__device__ float g_msg[BATCH * NAG * HDIM];

__device__ __forceinline__ u64 ffma2(u64 a, u64 b, u64 c) {
    u64 d;
    asm("fma.rn.f32x2 %0, %1, %2, %3;" : "=l"(d) : "l"(a), "l"(b), "l"(c));
    return d;
}
__device__ __forceinline__ u64 pack2(float lo, float hi) {
    u64 d;
    asm("mov.b64 %0, {%1, %2};" : "=l"(d) : "f"(lo), "f"(hi));
    return d;
}
__device__ __forceinline__ void unpack2(u64 v, float& lo, float& hi) {
    asm("mov.b64 {%0, %1}, %2;" : "=f"(lo), "=f"(hi) : "l"(v));
}

// K1: per (b,n): A_t = x @ W1_t[:16],  C_t = x @ W1_t[16:] + b1_t
__global__ __launch_bounds__(64) void k1_precompute(
    const float* __restrict__ x,
    const float* __restrict__ e0w1, const float* __restrict__ e0b1,
    const float* __restrict__ e1w1, const float* __restrict__ e1b1)
{
    int bn = blockIdx.x;
    int j  = threadIdx.x;
    __shared__ float xs[DN];
    if (j < DN) xs[j] = x[bn * DN + j];
    __syncthreads();

    float a0 = 0.f, a1 = 0.f;
    float c0 = e0b1[j], c1 = e1b1[j];
#pragma unroll
    for (int i = 0; i < DN; i++) {
        float xv = xs[i];
        a0 += xv * e0w1[i * HDIM + j];
        c0 += xv * e0w1[(DN + i) * HDIM + j];
        a1 += xv * e1w1[i * HDIM + j];
        c1 += xv * e1w1[(DN + i) * HDIM + j];
    }
    g_A0[bn * HDIM + j] = a0;
    g_C0[bn * HDIM + j] = c0;
    g_A1[bn * HDIM + j] = a1;
    g_C1[bn * HDIM + j] = c1;
}

// K2: block = one (b, recv), 128 threads = 4 warps:
//   warp (t, half): type t = wid>>1, j = (wid&1)*32 + lane.
// Thread owns one (t, j); W2 column prepacked into 32 b64 regs (k-pairs).
// Inner: for each sender s, y_tj = sum_k relu(A_t[s,k]+C_t[r,k]) * W2_t[k,j]
// via 32 FFMA2 on float2 k-pairs read from shared (LDS.128 broadcast).
__global__ __launch_bounds__(128) void k2_edges(
    const float* __restrict__ etypes,
    const float* __restrict__ e0w2, const float* __restrict__ e0b2,
    const float* __restrict__ e1w2, const float* __restrict__ e1b2)
{
    int br  = blockIdx.x;
    int b   = br >> 6;
    int r   = br & 63;
    int tid = threadIdx.x;
    int wid = tid >> 5;
    int lane = tid & 31;

    int t = wid >> 1;                 // type for compute phase
    int j = ((wid & 1) << 5) + lane;  // output dim for compute phase

    __shared__ __align__(16) float hbuf[2][SG][HDIM];
    __shared__ float wts[2][NAG];     // per-sender type weights (0 for s==r)
    __shared__ float msum[2][HDIM];

    // ---- one-time setup ----
    const float* w2t = t ? e1w2 : e0w2;
    u64 wreg[HDIM / 2];
#pragma unroll
    for (int kk = 0; kk < HDIM / 2; kk++)
        wreg[kk] = pack2(w2t[(2 * kk) * HDIM + j], w2t[(2 * kk + 1) * HDIM + j]);

    float b2j = (t ? e1b2 : e0b2)[j];

    // construct-phase mapping: ct = tid>>6, jc = tid&63
    int ct = tid >> 6;
    int jc = tid & 63;
    const float* Act = (ct ? g_A1 : g_A0) + (long)(b * NAG) * HDIM;
    float cc = (ct ? g_C1 : g_C0)[br * HDIM + jc];

    // edge-type weights into shared: tid covers (tw = tid>>6, s = tid&63)
    {
        int s = tid & 63;
        int tw = tid >> 6;
        float w = 0.f;
        if (s != r) {
            int e = s * 63 + r - (r > s ? 1 : 0);
            w = etypes[((long)b * NEDGE + e) * 3 + 1 + tw];
        }
        wts[tw][s] = w;
    }

    float msg = 0.f;

    for (int s0 = 0; s0 < NAG; s0 += SG) {
        __syncthreads();   // previous group's reads of hbuf complete
#pragma unroll
        for (int ss = 0; ss < SG; ss++)
            hbuf[ct][ss][jc] = fmaxf(Act[(s0 + ss) * HDIM + jc] + cc, 0.f);
        __syncthreads();   // hbuf ready

#pragma unroll
        for (int ss = 0; ss < SG; ss++) {
            const ulonglong2* hrow = (const ulonglong2*)hbuf[t][ss];
            u64 acc0 = pack2(0.f, 0.f);
            u64 acc1 = acc0;
#pragma unroll
            for (int kk = 0; kk < 16; kk++) {
                ulonglong2 hv = hrow[kk];
                acc0 = ffma2(hv.x, wreg[2 * kk],     acc0);
                acc1 = ffma2(hv.y, wreg[2 * kk + 1], acc1);
            }
            float l0, h0, l1, h1;
            unpack2(acc0, l0, h0);
            unpack2(acc1, l1, h1);
            float y = ((l0 + l1) + (h0 + h1)) + b2j;
            msg = fmaf(wts[t][s0 + ss], fmaxf(y, 0.f), msg);
        }
    }

    msum[t][j] = msg;
    __syncthreads();
    if (tid < HDIM)
        g_msg[br * HDIM + tid] = msum[0][tid] + msum[1][tid];
}

// K3: decoder per (b,n): relu(relu([x, msg] @ W1 + b1) @ W2 + b2)
__global__ __launch_bounds__(64) void k3_decode(
    const float* __restrict__ x,
    const float* __restrict__ ndw1, const float* __restrict__ ndb1,
    const float* __restrict__ ndw2, const float* __restrict__ ndb2,
    float* __restrict__ out)
{
    int bn = blockIdx.x;
    int j  = threadIdx.x;
    __shared__ float xs[DN];
    __shared__ float ms[HDIM];
    __shared__ float hs[HDIM];

    if (j < DN) xs[j] = x[bn * DN + j];
    ms[j] = g_msg[bn * HDIM + j];
    __syncthreads();

    float h = ndb1[j];
#pragma unroll
    for (int i = 0; i < DN; i++)   h += xs[i] * ndw1[i * HDIM + j];
#pragma unroll
    for (int i = 0; i < HDIM; i++) h += ms[i] * ndw1[(DN + i) * HDIM + j];
    hs[j] = fmaxf(h, 0.f);
    __syncthreads();

    if (j < DOUT) {
        float o = ndb2[j];
#pragma unroll
        for (int i = 0; i < HDIM; i++) o += hs[i] * ndw2[i * DOUT + j];
        out[bn * DOUT + j] = fmaxf(o, 0.f);
    }
}

extern "C" void kernel_launch(void* const* d_in, const int* in_sizes, int n_in,
                              void* d_out, int out_size)
{
    const float* node_states = (const float*)d_in[0];
    const float* edge_types  = (const float*)d_in[1];
    const float* e0_w1 = (const float*)d_in[2];
    const float* e0_b1 = (const float*)d_in[3];
    const float* e0_w2 = (const float*)d_in[4];
    const float* e0_b2 = (const float*)d_in[5];
    const float* e1_w1 = (const float*)d_in[6];
    const float* e1_b1 = (const float*)d_in[7];
    const float* e1_w2 = (const float*)d_in[8];
    const float* e1_b2 = (const float*)d_in[9];
    const float* nd_w1 = (const float*)d_in[10];
    const float* nd_b1 = (const float*)d_in[11];
    const float* nd_w2 = (const float*)d_in[12];
    const float* nd_b2 = (const float*)d_in[13];
    float* out = (float*)d_out;

    k1_precompute<<<BATCH * NAG, 64>>>(node_states, e0_w1, e0_b1, e1_w1, e1_b1);
    k2_edges<<<BATCH * NAG, 128>>>(edge_types, e0_w2, e0_b2, e1_w2, e1_b2);
    k3_decode<<<BATCH * NAG, 64>>>(node_states, nd_w1, nd_b1, nd_w2, nd_b2, out);
}

// round 3
// speedup vs baseline: 1.3416x; 1.0883x over previous
#include <cuda_runtime.h>

#define BATCH 128
#define NAG   64
#define NEDGE 4032
#define DN    16
#define HDIM  64
#define DOUT  16

typedef unsigned long long u64;

// Scratch (no cudaMalloc allowed)
__device__ float g_A0[BATCH * NAG * HDIM];
__device__ float g_C0[BATCH * NAG * HDIM];
__device__ float g_A1[BATCH * NAG * HDIM];
__device__ float g_C1[BATCH * NAG * HDIM];
__device__ float g_msg[BATCH * NAG * HDIM];

__device__ __forceinline__ u64 ffma2(u64 a, u64 b, u64 c) {
    u64 d;
    asm("fma.rn.f32x2 %0, %1, %2, %3;" : "=l"(d) : "l"(a), "l"(b), "l"(c));
    return d;
}
__device__ __forceinline__ u64 pack2(float lo, float hi) {
    u64 d;
    asm("mov.b64 %0, {%1, %2};" : "=l"(d) : "f"(lo), "f"(hi));
    return d;
}
__device__ __forceinline__ void unpack2(u64 v, float& lo, float& hi) {
    asm("mov.b64 {%0, %1}, %2;" : "=f"(lo), "=f"(hi) : "l"(v));
}

// K1: per (b,n): A_t = x @ W1_t[:16],  C_t = x @ W1_t[16:] + b1_t
__global__ __launch_bounds__(64) void k1_precompute(
    const float* __restrict__ x,
    const float* __restrict__ e0w1, const float* __restrict__ e0b1,
    const float* __restrict__ e1w1, const float* __restrict__ e1b1)
{
    int bn = blockIdx.x;
    int j  = threadIdx.x;
    __shared__ float xs[DN];
    if (j < DN) xs[j] = x[bn * DN + j];
    __syncthreads();

    float a0 = 0.f, a1 = 0.f;
    float c0 = e0b1[j], c1 = e1b1[j];
#pragma unroll
    for (int i = 0; i < DN; i++) {
        float xv = xs[i];
        a0 += xv * e0w1[i * HDIM + j];
        c0 += xv * e0w1[(DN + i) * HDIM + j];
        a1 += xv * e1w1[i * HDIM + j];
        c1 += xv * e1w1[(DN + i) * HDIM + j];
    }
    g_A0[bn * HDIM + j] = a0;
    g_C0[bn * HDIM + j] = c0;
    g_A1[bn * HDIM + j] = a1;
    g_C1[bn * HDIM + j] = c1;
}

// K2: block = one (b, recv), 128 threads = 4 warps (t = wid>>1, j = (wid&1)*32+lane).
// Phase 1 (once per block): build hbuf[t][s][k] = relu(A_t[b,s,k] + C_t[b,r,k])
//   for ALL 64 senders via 16 independent LDG.128 per thread (MLP=16).
// Phase 2 (barrier-free): per warp, loop 64 senders: 16 LDS.128 broadcast + 32 FFMA2.
__global__ __launch_bounds__(128) void k2_edges(
    const float* __restrict__ etypes,
    const float* __restrict__ e0w2, const float* __restrict__ e0b2,
    const float* __restrict__ e1w2, const float* __restrict__ e1b2)
{
    int br   = blockIdx.x;
    int b    = br >> 6;
    int r    = br & 63;
    int tid  = threadIdx.x;
    int wid  = tid >> 5;
    int lane = tid & 31;

    int t = wid >> 1;
    int j = ((wid & 1) << 5) + lane;

    __shared__ __align__(16) float hbuf[2][NAG][HDIM];   // 32 KB
    __shared__ __align__(16) float cbuf[2][HDIM];
    __shared__ float wts[2][NAG];
    __shared__ float msum[2][HDIM];

    // ---- load per-r C values + edge-type weights ----
    {
        int tt = tid >> 6, k = tid & 63;
        cbuf[tt][k] = (tt ? g_C1 : g_C0)[br * HDIM + k];

        int s = k;
        float w = 0.f;
        if (s != r) {
            int e = s * 63 + r - (r > s ? 1 : 0);   // np.where(ones-eye) ordering
            w = etypes[((long)b * NEDGE + e) * 3 + 1 + tt];
        }
        wts[tt][s] = w;
    }

    // ---- register-cache W2 column for (t, j): 32 packed b64 ----
    const float* w2t = t ? e1w2 : e0w2;
    u64 wreg[HDIM / 2];
#pragma unroll
    for (int kk = 0; kk < HDIM / 2; kk++)
        wreg[kk] = pack2(w2t[(2 * kk) * HDIM + j], w2t[(2 * kk + 1) * HDIM + j]);
    float b2j = (t ? e1b2 : e0b2)[j];

    __syncthreads();   // cbuf ready

    // ---- phase 1: construct hbuf for all senders, both types ----
    // 2048 float4 elements; thread handles 16 (all independent LDGs).
    {
        const float4* A04 = (const float4*)(g_A0 + (long)(b * NAG) * HDIM);
        const float4* A14 = (const float4*)(g_A1 + (long)(b * NAG) * HDIM);
        float4* hb4 = (float4*)hbuf;
        const float4* cb4 = (const float4*)cbuf;
#pragma unroll
        for (int it = 0; it < 16; it++) {
            int idx = it * 128 + tid;        // float4 index into hbuf
            int tt  = idx >> 10;             // uniform per iteration
            int rem = idx & 1023;            // s*16 + k4
            float4 a = (tt ? A14 : A04)[rem];
            float4 c = cb4[tt * 16 + (idx & 15)];
            float4 h;
            h.x = fmaxf(a.x + c.x, 0.f);
            h.y = fmaxf(a.y + c.y, 0.f);
            h.z = fmaxf(a.z + c.z, 0.f);
            h.w = fmaxf(a.w + c.w, 0.f);
            hb4[idx] = h;
        }
    }
    __syncthreads();   // hbuf ready

    // ---- phase 2: barrier-free sender loop ----
    float msg = 0.f;
#pragma unroll 4
    for (int s = 0; s < NAG; s++) {
        const ulonglong2* hrow = (const ulonglong2*)hbuf[t][s];
        u64 acc0 = pack2(0.f, 0.f);
        u64 acc1 = acc0;
#pragma unroll
        for (int kk = 0; kk < 16; kk++) {
            ulonglong2 hv = hrow[kk];
            acc0 = ffma2(hv.x, wreg[2 * kk],     acc0);
            acc1 = ffma2(hv.y, wreg[2 * kk + 1], acc1);
        }
        float l0, h0, l1, h1;
        unpack2(acc0, l0, h0);
        unpack2(acc1, l1, h1);
        float y = ((l0 + l1) + (h0 + h1)) + b2j;
        msg = fmaf(wts[t][s], fmaxf(y, 0.f), msg);
    }

    msum[t][j] = msg;
    __syncthreads();
    if (tid < HDIM)
        g_msg[br * HDIM + tid] = msum[0][tid] + msum[1][tid];
}

// K3: decoder per (b,n): relu(relu([x, msg] @ W1 + b1) @ W2 + b2)
__global__ __launch_bounds__(64) void k3_decode(
    const float* __restrict__ x,
    const float* __restrict__ ndw1, const float* __restrict__ ndb1,
    const float* __restrict__ ndw2, const float* __restrict__ ndb2,
    float* __restrict__ out)
{
    int bn = blockIdx.x;
    int j  = threadIdx.x;
    __shared__ float xs[DN];
    __shared__ float ms[HDIM];
    __shared__ float hs[HDIM];

    if (j < DN) xs[j] = x[bn * DN + j];
    ms[j] = g_msg[bn * HDIM + j];
    __syncthreads();

    float h = ndb1[j];
#pragma unroll
    for (int i = 0; i < DN; i++)   h += xs[i] * ndw1[i * HDIM + j];
#pragma unroll
    for (int i = 0; i < HDIM; i++) h += ms[i] * ndw1[(DN + i) * HDIM + j];
    hs[j] = fmaxf(h, 0.f);
    __syncthreads();

    if (j < DOUT) {
        float o = ndb2[j];
#pragma unroll
        for (int i = 0; i < HDIM; i++) o += hs[i] * ndw2[i * DOUT + j];
        out[bn * DOUT + j] = fmaxf(o, 0.f);
    }
}

extern "C" void kernel_launch(void* const* d_in, const int* in_sizes, int n_in,
                              void* d_out, int out_size)
{
    const float* node_states = (const float*)d_in[0];
    const float* edge_types  = (const float*)d_in[1];
    const float* e0_w1 = (const float*)d_in[2];
    const float* e0_b1 = (const float*)d_in[3];
    const float* e0_w2 = (const float*)d_in[4];
    const float* e0_b2 = (const float*)d_in[5];
    const float* e1_w1 = (const float*)d_in[6];
    const float* e1_b1 = (const float*)d_in[7];
    const float* e1_w2 = (const float*)d_in[8];
    const float* e1_b2 = (const float*)d_in[9];
    const float* nd_w1 = (const float*)d_in[10];
    const float* nd_b1 = (const float*)d_in[11];
    const float* nd_w2 = (const float*)d_in[12];
    const float* nd_b2 = (const float*)d_in[13];
    float* out = (float*)d_out;

    k1_precompute<<<BATCH * NAG, 64>>>(node_states, e0_w1, e0_b1, e1_w1, e1_b1);
    k2_edges<<<BATCH * NAG, 128>>>(edge_types, e0_w2, e0_b2, e1_w2, e1_b2);
    k3_decode<<<BATCH * NAG, 64>>>(node_states, nd_w1, nd_b1, nd_w2, nd_b2, out);
}

// round 4
// speedup vs baseline: 1.6338x; 1.2178x over previous
#include <cuda_runtime.h>

#define BATCH 128
#define NAG   64
#define NEDGE 4032
#define DN    16
#define HDIM  64
#define DOUT  16

typedef unsigned long long u64;

// Scratch (no cudaMalloc allowed)
__device__ float g_A0[BATCH * NAG * HDIM];
__device__ float g_C0[BATCH * NAG * HDIM];
__device__ float g_A1[BATCH * NAG * HDIM];
__device__ float g_C1[BATCH * NAG * HDIM];

__device__ __forceinline__ u64 ffma2(u64 a, u64 b, u64 c) {
    u64 d;
    asm("fma.rn.f32x2 %0, %1, %2, %3;" : "=l"(d) : "l"(a), "l"(b), "l"(c));
    return d;
}
__device__ __forceinline__ u64 pack2(float lo, float hi) {
    u64 d;
    asm("mov.b64 %0, {%1, %2};" : "=l"(d) : "f"(lo), "f"(hi));
    return d;
}
__device__ __forceinline__ void unpack2(u64 v, float& lo, float& hi) {
    asm("mov.b64 {%0, %1}, %2;" : "=f"(lo), "=f"(hi) : "l"(v));
}

// K1: per (b,n): A_t = x @ W1_t[:16],  C_t = x @ W1_t[16:] + b1_t
__global__ __launch_bounds__(64) void k1_precompute(
    const float* __restrict__ x,
    const float* __restrict__ e0w1, const float* __restrict__ e0b1,
    const float* __restrict__ e1w1, const float* __restrict__ e1b1)
{
    int bn = blockIdx.x;
    int j  = threadIdx.x;
    __shared__ float xs[DN];
    if (j < DN) xs[j] = x[bn * DN + j];
    __syncthreads();

    float a0 = 0.f, a1 = 0.f;
    float c0 = e0b1[j], c1 = e1b1[j];
#pragma unroll
    for (int i = 0; i < DN; i++) {
        float xv = xs[i];
        a0 += xv * e0w1[i * HDIM + j];
        c0 += xv * e0w1[(DN + i) * HDIM + j];
        a1 += xv * e1w1[i * HDIM + j];
        c1 += xv * e1w1[(DN + i) * HDIM + j];
    }
    g_A0[bn * HDIM + j] = a0;
    g_C0[bn * HDIM + j] = c0;
    g_A1[bn * HDIM + j] = a1;
    g_C1[bn * HDIM + j] = c1;
}

// K2 (fused edges + decoder): block = one (b, recv), 64 threads = 2 warps.
//   warp t handles edge type t; thread owns TWO output cols j0=lane, j1=lane+32
//   (each LDS.128 of h feeds 4 FFMA2).
// After message reduction, the same block runs the node decoder for node r.
__global__ __launch_bounds__(64) void k2_fused(
    const float* __restrict__ x,
    const float* __restrict__ etypes,
    const float* __restrict__ e0w2, const float* __restrict__ e0b2,
    const float* __restrict__ e1w2, const float* __restrict__ e1b2,
    const float* __restrict__ ndw1, const float* __restrict__ ndb1,
    const float* __restrict__ ndw2, const float* __restrict__ ndb2,
    float* __restrict__ out)
{
    int br   = blockIdx.x;
    int b    = br >> 6;
    int r    = br & 63;
    int tid  = threadIdx.x;
    int t    = tid >> 5;       // warp = edge type
    int lane = tid & 31;
    int j0   = lane;
    int j1   = lane + 32;

    __shared__ __align__(16) float hbuf[2][NAG][HDIM];   // 32 KB
    __shared__ __align__(16) float cbuf[2][HDIM];
    __shared__ float wts[2][NAG];
    __shared__ float msum[2][HDIM];
    __shared__ float ms[HDIM];           // combined message
    __shared__ float xs[DN];
    __shared__ float hs[HDIM];           // decoder hidden

    // ---- C values, edge-type weights, x ----
#pragma unroll
    for (int tt = 0; tt < 2; tt++) {
        int k = tid;
        cbuf[tt][k] = (tt ? g_C1 : g_C0)[br * HDIM + k];
        int s = k;
        float w = 0.f;
        if (s != r) {
            int e = s * 63 + r - (r > s ? 1 : 0);   // np.where(ones-eye) ordering
            w = etypes[((long)b * NEDGE + e) * 3 + 1 + tt];
        }
        wts[tt][s] = w;
    }
    if (tid < DN) xs[tid] = x[br * DN + tid];

    // ---- register-cache W2 columns j0 and j1 for type t (64 packed b64) ----
    const float* w2t = t ? e1w2 : e0w2;
    u64 wA[HDIM / 2], wB[HDIM / 2];
#pragma unroll
    for (int kk = 0; kk < HDIM / 2; kk++) {
        wA[kk] = pack2(w2t[(2 * kk) * HDIM + j0], w2t[(2 * kk + 1) * HDIM + j0]);
        wB[kk] = pack2(w2t[(2 * kk) * HDIM + j1], w2t[(2 * kk + 1) * HDIM + j1]);
    }
    const float* b2t = t ? e1b2 : e0b2;
    float b2a = b2t[j0], b2b = b2t[j1];

    __syncthreads();   // cbuf ready

    // ---- phase 1: hbuf[t][s][k] = relu(A_t[b,s,k] + C_t[b,r,k]) for all s ----
    {
        const float4* A04 = (const float4*)(g_A0 + (long)(b * NAG) * HDIM);
        const float4* A14 = (const float4*)(g_A1 + (long)(b * NAG) * HDIM);
        float4* hb4 = (float4*)hbuf;
        const float4* cb4 = (const float4*)cbuf;
#pragma unroll
        for (int it = 0; it < 32; it++) {
            int idx = it * 64 + tid;         // float4 index into hbuf (2048 total)
            int tt  = idx >> 10;             // uniform per iteration
            int rem = idx & 1023;            // s*16 + k4
            float4 a = (tt ? A14 : A04)[rem];
            float4 c = cb4[tt * 16 + (idx & 15)];
            float4 h;
            h.x = fmaxf(a.x + c.x, 0.f);
            h.y = fmaxf(a.y + c.y, 0.f);
            h.z = fmaxf(a.z + c.z, 0.f);
            h.w = fmaxf(a.w + c.w, 0.f);
            hb4[idx] = h;
        }
    }
    __syncthreads();   // hbuf ready

    // ---- phase 2: barrier-free sender loop; 16 LDS.128 -> 64 FFMA2 ----
    float msgA = 0.f, msgB = 0.f;
#pragma unroll 2
    for (int s = 0; s < NAG; s++) {
        const ulonglong2* hrow = (const ulonglong2*)hbuf[t][s];
        u64 ac0 = pack2(0.f, 0.f), ac1 = ac0;   // col j0
        u64 bc0 = ac0, bc1 = ac0;               // col j1
#pragma unroll
        for (int kk = 0; kk < 16; kk++) {
            ulonglong2 hv = hrow[kk];
            ac0 = ffma2(hv.x, wA[2 * kk],     ac0);
            bc0 = ffma2(hv.x, wB[2 * kk],     bc0);
            ac1 = ffma2(hv.y, wA[2 * kk + 1], ac1);
            bc1 = ffma2(hv.y, wB[2 * kk + 1], bc1);
        }
        float wt = wts[t][s];
        float p, q, u, v;
        unpack2(ac0, p, q); unpack2(ac1, u, v);
        float yA = ((p + u) + (q + v)) + b2a;
        unpack2(bc0, p, q); unpack2(bc1, u, v);
        float yB = ((p + u) + (q + v)) + b2b;
        msgA = fmaf(wt, fmaxf(yA, 0.f), msgA);
        msgB = fmaf(wt, fmaxf(yB, 0.f), msgB);
    }

    msum[t][j0] = msgA;
    msum[t][j1] = msgB;
    __syncthreads();

    // ---- fused decoder for node (b, r) ----
    ms[tid] = msum[0][tid] + msum[1][tid];
    __syncthreads();

    {
        int j = tid;
        float h = ndb1[j];
#pragma unroll
        for (int i = 0; i < DN; i++)   h = fmaf(xs[i], ndw1[i * HDIM + j], h);
#pragma unroll
        for (int k = 0; k < HDIM; k++) h = fmaf(ms[k], ndw1[(DN + k) * HDIM + j], h);
        hs[j] = fmaxf(h, 0.f);
    }
    __syncthreads();

    if (tid < DOUT) {
        float o = ndb2[tid];
#pragma unroll
        for (int k = 0; k < HDIM; k++) o = fmaf(hs[k], ndw2[k * DOUT + tid], o);
        out[br * DOUT + tid] = fmaxf(o, 0.f);
    }
}

extern "C" void kernel_launch(void* const* d_in, const int* in_sizes, int n_in,
                              void* d_out, int out_size)
{
    const float* node_states = (const float*)d_in[0];
    const float* edge_types  = (const float*)d_in[1];
    const float* e0_w1 = (const float*)d_in[2];
    const float* e0_b1 = (const float*)d_in[3];
    const float* e0_w2 = (const float*)d_in[4];
    const float* e0_b2 = (const float*)d_in[5];
    const float* e1_w1 = (const float*)d_in[6];
    const float* e1_b1 = (const float*)d_in[7];
    const float* e1_w2 = (const float*)d_in[8];
    const float* e1_b2 = (const float*)d_in[9];
    const float* nd_w1 = (const float*)d_in[10];
    const float* nd_b1 = (const float*)d_in[11];
    const float* nd_w2 = (const float*)d_in[12];
    const float* nd_b2 = (const float*)d_in[13];
    float* out = (float*)d_out;

    k1_precompute<<<BATCH * NAG, 64>>>(node_states, e0_w1, e0_b1, e1_w1, e1_b1);
    k2_fused<<<BATCH * NAG, 64>>>(node_states, edge_types,
                                  e0_w2, e0_b2, e1_w2, e1_b2,
                                  nd_w1, nd_b1, nd_w2, nd_b2, out);
}